// round 1
// baseline (speedup 1.0000x reference)
#include <cuda_runtime.h>
#include <cuda_bf16.h>
#include <stdint.h>

// ---------------------------------------------------------------------------
// MMD loss, restructured:
//   sum(L2) = 2*M*sum_i ||x_i||^2 - 2*||sum_i x_i||^2   (M = 8192)
//   bw      = sum(L2)/(M^2-M)/4
//   e       = exp(-L2/(16*bw));  5-kernel sum = e + e^2 + e^4 + e^8 + e^16
//   loss    = -2 * mean_{i,j in cross block}(kernel sum)
// Only the 4096x4096 source x target^T gram block is computed (symmetry).
// ---------------------------------------------------------------------------

#define NROWS 4096
#define D     256
#define M_TOT 8192

__device__ float g_sq[M_TOT];                 // per-row squared norms (src then tgt)
__device__ float g_colsum_part[64][256];      // partial column sums
__device__ float g_inv_b16;                   // 1/(16*bw)
__device__ float g_part[1024];                // per-block kernel-sum partials

// ---------------------------------------------------------------------------
// packed f32x2 helpers (Blackwell)
// ---------------------------------------------------------------------------
__device__ __forceinline__ unsigned long long fma2(unsigned long long a,
                                                   unsigned long long b,
                                                   unsigned long long c) {
    unsigned long long d;
    asm("fma.rn.f32x2 %0, %1, %2, %3;" : "=l"(d) : "l"(a), "l"(b), "l"(c));
    return d;
}
__device__ __forceinline__ unsigned long long pack2(float x) {
    unsigned long long d;
    unsigned int xi = __float_as_uint(x);
    asm("mov.b64 %0, {%1, %1};" : "=l"(d) : "r"(xi));
    return d;
}

__device__ __forceinline__ const float* row_ptr(const float* src, const float* tgt, int row) {
    return (row < NROWS) ? (src + (size_t)row * D) : (tgt + (size_t)(row - NROWS) * D);
}

// ---------------------------------------------------------------------------
// Kernel 1: per-row squared norms + partial column sums.
// 64 blocks x 256 threads; block handles 128 consecutive rows of [src; tgt].
// ---------------------------------------------------------------------------
__global__ void stats_kernel(const float* __restrict__ src, const float* __restrict__ tgt) {
    const int blk = blockIdx.x;      // 0..63
    const int tid = threadIdx.x;     // 0..255
    const int base = blk * 128;

    // partial column sum: thread d accumulates column d over the block's rows
    float s = 0.f;
    for (int r = 0; r < 128; r++) {
        const float* p = row_ptr(src, tgt, base + r);
        s += p[tid];
    }
    g_colsum_part[blk][tid] = s;

    // row squared norms: one warp per row, 16 rows per warp
    const int w = tid >> 5, lane = tid & 31;
    for (int r = 0; r < 16; r++) {
        const int row = base + w * 16 + r;
        const float4* p4 = (const float4*)row_ptr(src, tgt, row);
        float4 a = p4[lane];
        float4 b = p4[lane + 32];
        float sq = a.x*a.x + a.y*a.y + a.z*a.z + a.w*a.w
                 + b.x*b.x + b.y*b.y + b.z*b.z + b.w*b.w;
        #pragma unroll
        for (int off = 16; off > 0; off >>= 1)
            sq += __shfl_xor_sync(0xffffffffu, sq, off);
        if (lane == 0) g_sq[row] = sq;
    }
}

// ---------------------------------------------------------------------------
// Kernel 2: finish bandwidth. 1 block x 256 threads.
// ---------------------------------------------------------------------------
__global__ void bw_kernel() {
    const int tid = threadIdx.x;
    __shared__ double r1[256];  // ||colsum||^2 partials
    __shared__ double r2[256];  // sum of row norms partials

    float s = 0.f;
    #pragma unroll 8
    for (int p = 0; p < 64; p++) s += g_colsum_part[p][tid];
    double ssq = (double)s * (double)s;

    double sumsq = 0.0;
    #pragma unroll 8
    for (int m = 0; m < M_TOT / 256; m++) sumsq += (double)g_sq[tid + m * 256];

    r1[tid] = ssq;
    r2[tid] = sumsq;
    __syncthreads();
    for (int st = 128; st > 0; st >>= 1) {
        if (tid < st) { r1[tid] += r1[tid + st]; r2[tid] += r2[tid + st]; }
        __syncthreads();
    }
    if (tid == 0) {
        const double M = (double)M_TOT;
        double sumL2 = 2.0 * M * r2[0] - 2.0 * r1[0];
        double bw = sumL2 / (M * M - M);
        bw = bw / 4.0;                       // KERNEL_MUL^(KERNEL_NUM/2) = 2^2
        g_inv_b16 = (float)(1.0 / (bw * 16.0));
    }
}

// ---------------------------------------------------------------------------
// Kernel 3: fused GEMM (source @ target^T) + multi-bandwidth kernel epilogue.
// 128x128 tile per block, 256 threads, 8x8 per thread, f32x2 packed FMA.
// ---------------------------------------------------------------------------
__device__ __forceinline__ float kern5(float L2, float inv_b16) {
    float e  = __expf(-L2 * inv_b16);  // exp(-L2/(16*bw)) = widest-bandwidth kernel
    float e2 = e * e;
    float e4 = e2 * e2;
    float e8 = e4 * e4;
    return e + e2 + e4 + e8 + e8 * e8;
}

__global__ __launch_bounds__(256, 2)
void mmd_gemm_kernel(const float* __restrict__ A, const float* __restrict__ B) {
    __shared__ float As[8][128];
    __shared__ float Bs[8][128];

    const int tid = threadIdx.x;
    const int tx = tid & 15;          // 0..15 -> N direction
    const int ty = tid >> 4;          // 0..15 -> M direction
    const int lrow = tid >> 1;        // 0..127 (loader row)
    const int lseg = (tid & 1) * 4;   // 0 or 4  (loader k-segment)

    const float* Ag = A + (size_t)(blockIdx.y * 128 + lrow) * D + lseg;
    const float* Bg = B + (size_t)(blockIdx.x * 128 + lrow) * D + lseg;

    unsigned long long acc[8][4];
    #pragma unroll
    for (int i = 0; i < 8; i++)
        #pragma unroll
        for (int j = 0; j < 4; j++) acc[i][j] = 0ull;

    for (int k0 = 0; k0 < D; k0 += 8) {
        float4 av = *(const float4*)(Ag + k0);
        float4 bv = *(const float4*)(Bg + k0);
        __syncthreads();  // previous tile fully consumed
        As[lseg + 0][lrow] = av.x; As[lseg + 1][lrow] = av.y;
        As[lseg + 2][lrow] = av.z; As[lseg + 3][lrow] = av.w;
        Bs[lseg + 0][lrow] = bv.x; Bs[lseg + 1][lrow] = bv.y;
        Bs[lseg + 2][lrow] = bv.z; Bs[lseg + 3][lrow] = bv.w;
        __syncthreads();

        #pragma unroll
        for (int k = 0; k < 8; k++) {
            float a[8];
            unsigned long long b[4];
            #pragma unroll
            for (int i = 0; i < 8; i++) a[i] = As[k][ty * 8 + i];
            #pragma unroll
            for (int j = 0; j < 4; j++)
                b[j] = *(const unsigned long long*)&Bs[k][tx * 8 + j * 2];
            #pragma unroll
            for (int i = 0; i < 8; i++) {
                unsigned long long aa = pack2(a[i]);
                #pragma unroll
                for (int j = 0; j < 4; j++)
                    acc[i][j] = fma2(aa, b[j], acc[i][j]);
            }
        }
    }

    // epilogue: L2 -> 5-kernel sum, accumulate
    const float inv_b16 = g_inv_b16;
    const int grow = blockIdx.y * 128 + ty * 8;
    const int gcol = blockIdx.x * 128 + tx * 8;

    float tj[8];
    #pragma unroll
    for (int j = 0; j < 8; j++) tj[j] = g_sq[NROWS + gcol + j];

    float ksum = 0.f;
    #pragma unroll
    for (int i = 0; i < 8; i++) {
        const float si = g_sq[grow + i];
        #pragma unroll
        for (int j4 = 0; j4 < 4; j4++) {
            float2 c = *reinterpret_cast<float2*>(&acc[i][j4]);
            ksum += kern5(si + tj[2 * j4]     - 2.f * c.x, inv_b16);
            ksum += kern5(si + tj[2 * j4 + 1] - 2.f * c.y, inv_b16);
        }
    }

    __shared__ float red[256];
    red[tid] = ksum;
    __syncthreads();
    for (int st = 128; st > 0; st >>= 1) {
        if (tid < st) red[tid] += red[tid + st];
        __syncthreads();
    }
    if (tid == 0) g_part[blockIdx.y * gridDim.x + blockIdx.x] = red[0];
}

// ---------------------------------------------------------------------------
// Kernel 4: final reduction -> loss
// ---------------------------------------------------------------------------
__global__ void finish_kernel(float* __restrict__ out) {
    const int tid = threadIdx.x;
    __shared__ double red[256];
    double s = 0.0;
    #pragma unroll
    for (int m = 0; m < 4; m++) s += (double)g_part[tid + m * 256];
    red[tid] = s;
    __syncthreads();
    for (int st = 128; st > 0; st >>= 1) {
        if (tid < st) red[tid] += red[tid + st];
        __syncthreads();
    }
    if (tid == 0) {
        double mean = red[0] / ((double)NROWS * (double)NROWS);
        out[0] = (float)(-2.0 * mean);
    }
}

// ---------------------------------------------------------------------------
extern "C" void kernel_launch(void* const* d_in, const int* in_sizes, int n_in,
                              void* d_out, int out_size) {
    (void)in_sizes; (void)n_in; (void)out_size;
    const float* src = (const float*)d_in[0];
    const float* tgt = (const float*)d_in[1];
    float* out = (float*)d_out;

    stats_kernel<<<64, 256>>>(src, tgt);
    bw_kernel<<<1, 256>>>();
    mmd_gemm_kernel<<<dim3(32, 32), 256>>>(src, tgt);
    finish_kernel<<<1, 256>>>(out);
}

// round 3
// speedup vs baseline: 2.6047x; 2.6047x over previous
#include <cuda_runtime.h>
#include <stdint.h>

// ============================================================================
// MMD loss via classic tensor-core mma.sync (tf32) — family-portable PTX only
// (harness ptxas targets sm_103 without the 'a' suffix: no tcgen05/TMA).
//
//   sum(L2) = 2*M*sum||x_i||^2 - 2*||sum x_i||^2  (M=8192)
//   bw = sum(L2)/(M^2-M)/4 ; e = exp(-L2/(16 bw))
//   kernel sum = e + e^2 + e^4 + e^8 + e^16
//   loss = -2 * mean over 4096x4096 cross block
//
// Stage 1 (stats_kernel): row norms, col-sum partials, bandwidth (last block),
//   AND fragment-major permute of src/tgt into g_Aperm/g_Bperm.
// Stage 2 (mmd_mma_kernel): 128x128 tile GEMM via m16n8k8 tf32 mma.sync with
//   cp.async staging of permuted fragments, fused exp epilogue, final loss in
//   the last CTA.
// ============================================================================

#define NROWS 4096
#define D     256
#define M_TOT 8192

__device__ float g_sq[M_TOT];
__device__ float g_colsum_part[64][256];
__device__ float g_inv_b16;
__device__ float g_part[1024];
__device__ int   g_ctr1;
__device__ int   g_ctr2;
__device__ float g_Aperm[NROWS * D];   // [tile_m(256)][tile_k(32)][lane(32)][4]
__device__ float g_Bperm[NROWS * D];   // [pair(256)][tile_k(32)][lane(32)][4]

// ---------------------------------------------------------------------------
__device__ __forceinline__ uint32_t smem_u32(const void* p) {
    uint32_t a;
    asm("{ .reg .u64 t; cvta.to.shared.u64 t, %1; cvt.u32.u64 %0, t; }"
        : "=r"(a) : "l"(p));
    return a;
}
__device__ __forceinline__ void cp_async16(uint32_t s, const void* g) {
    asm volatile("cp.async.cg.shared.global [%0], [%1], 16;"
                 :: "r"(s), "l"(g) : "memory");
}
#define CP_COMMIT() asm volatile("cp.async.commit_group;" ::: "memory")
#define CP_WAIT(n)  asm volatile("cp.async.wait_group %0;" :: "n"(n) : "memory")

// m16n8k8 tf32 mma: D = A(16x8 row) * B(8x8 col) + D
__device__ __forceinline__ void mma_tf32(float* c, uint32_t a0, uint32_t a1,
                                         uint32_t a2, uint32_t a3,
                                         uint32_t b0, uint32_t b1) {
    asm volatile(
        "mma.sync.aligned.m16n8k8.row.col.f32.tf32.tf32.f32 "
        "{%0,%1,%2,%3}, {%4,%5,%6,%7}, {%8,%9}, {%0,%1,%2,%3};"
        : "+f"(c[0]), "+f"(c[1]), "+f"(c[2]), "+f"(c[3])
        : "r"(a0), "r"(a1), "r"(a2), "r"(a3), "r"(b0), "r"(b1));
}

__device__ __forceinline__ const float* row_ptr(const float* s, const float* t, int r) {
    return (r < NROWS) ? (s + (size_t)r * D) : (t + (size_t)(r - NROWS) * D);
}

// ---------------------------------------------------------------------------
// Kernel 1: stats + fragment permute. 64 blocks x 256 threads, 128 rows/block.
// ---------------------------------------------------------------------------
__global__ void stats_kernel(const float* __restrict__ src, const float* __restrict__ tgt) {
    const int blk = blockIdx.x, tid = threadIdx.x;
    const int base = blk * 128;
    const int w = tid >> 5, lane = tid & 31;
    const int g = lane >> 2, t = lane & 3;

    // column-sum partials
    float s = 0.f;
    for (int r = 0; r < 128; r++) s += row_ptr(src, tgt, base + r)[tid];
    g_colsum_part[blk][tid] = s;

    // row squared norms (one warp per 16 rows)
    for (int r = 0; r < 16; r++) {
        const int row = base + w * 16 + r;
        const float4* p4 = (const float4*)row_ptr(src, tgt, row);
        float4 a = p4[lane], b = p4[lane + 32];
        float sq = a.x*a.x + a.y*a.y + a.z*a.z + a.w*a.w
                 + b.x*b.x + b.y*b.y + b.z*b.z + b.w*b.w;
        #pragma unroll
        for (int off = 16; off > 0; off >>= 1) sq += __shfl_xor_sync(0xffffffffu, sq, off);
        if (lane == 0) g_sq[row] = sq;
    }

    // fragment-major permute. Fragment maps (m16n8k8 tf32, row.col):
    //   A: a0=(g,t) a1=(g+8,t) a2=(g,t+4) a3=(g+8,t+4)   [row=m, col=k]
    //   B: b0=(k=t, n=g) b1=(k=t+4, n=g); pack two n-tiles per 4-reg block.
    if (blk < 32) {
        const float* bp = src + (size_t)(base + w * 16) * D;
        const int tile_m = blk * 8 + w;
        float4* dst = (float4*)g_Aperm + (size_t)tile_m * 32 * 32 + lane;
        #pragma unroll 4
        for (int tk = 0; tk < 32; tk++) {
            float4 v;
            v.x = bp[(size_t)g       * D + tk * 8 + t];
            v.y = bp[(size_t)(g + 8) * D + tk * 8 + t];
            v.z = bp[(size_t)g       * D + tk * 8 + t + 4];
            v.w = bp[(size_t)(g + 8) * D + tk * 8 + t + 4];
            dst[tk * 32] = v;
        }
    } else {
        const float* bp = tgt + (size_t)((base - NROWS) + w * 16) * D;
        const int pair = (blk - 32) * 8 + w;
        float4* dst = (float4*)g_Bperm + (size_t)pair * 32 * 32 + lane;
        #pragma unroll 4
        for (int tk = 0; tk < 32; tk++) {
            float4 v;
            v.x = bp[(size_t)g       * D + tk * 8 + t];       // b0 of n-tile 2p
            v.y = bp[(size_t)g       * D + tk * 8 + t + 4];   // b1 of n-tile 2p
            v.z = bp[(size_t)(g + 8) * D + tk * 8 + t];       // b0 of n-tile 2p+1
            v.w = bp[(size_t)(g + 8) * D + tk * 8 + t + 4];   // b1 of n-tile 2p+1
            dst[tk * 32] = v;
        }
    }

    // last-block tail: bandwidth
    __shared__ int is_last;
    __threadfence();
    if (tid == 0) is_last = (atomicAdd(&g_ctr1, 1) == 63);
    __syncthreads();
    if (!is_last) return;
    __threadfence();

    __shared__ double r1[256], r2[256];
    float cs = 0.f;
    #pragma unroll 8
    for (int p = 0; p < 64; p++) cs += g_colsum_part[p][tid];
    double ssq = (double)cs * (double)cs;
    double sumsq = 0.0;
    #pragma unroll 8
    for (int m = 0; m < M_TOT / 256; m++) sumsq += (double)g_sq[tid + m * 256];
    r1[tid] = ssq; r2[tid] = sumsq;
    __syncthreads();
    for (int st = 128; st > 0; st >>= 1) {
        if (tid < st) { r1[tid] += r1[tid + st]; r2[tid] += r2[tid + st]; }
        __syncthreads();
    }
    if (tid == 0) {
        const double M = (double)M_TOT;
        double sumL2 = 2.0 * M * r2[0] - 2.0 * r1[0];
        double bw = sumL2 / (M * M - M) / 4.0;
        g_inv_b16 = (float)(1.0 / (bw * 16.0));
        g_ctr1 = 0;   // reset for graph replay
    }
}

// ---------------------------------------------------------------------------
// Kernel 2: tf32 mma.sync GEMM + fused exp epilogue. 1024 CTAs x 256 threads.
// 128x128 tile, k-chunks of 32, 2-stage cp.async double buffer.
// ---------------------------------------------------------------------------
#define OPND_BYTES 16384                     // one operand, one chunk (128x32 f32)
#define BUF_BYTES  (2 * OPND_BYTES)
#define SMEM_TJ    (2 * BUF_BYTES)           // 65536
#define SMEM_RED   (SMEM_TJ + 512)
#define SMEM_TOT   (SMEM_RED + 64)

__global__ __launch_bounds__(256, 2)
void mmd_mma_kernel(float* __restrict__ out) {
    extern __shared__ char smem[];
    const uint32_t sb = smem_u32(smem);
    const int tid = threadIdx.x, wid = tid >> 5, lane = tid & 31;
    const int g = lane >> 2, t = lane & 3;
    const int warp_m = wid & 3, warp_n = wid >> 2;
    const int bx = blockIdx.x, by = blockIdx.y;

    // stage tj (col norms for this CTA's 128 cols)
    float* tjs = (float*)(smem + SMEM_TJ);
    if (tid < 128) tjs[tid] = g_sq[NROWS + bx * 128 + tid];

    float acc[2][8][4];
    #pragma unroll
    for (int i = 0; i < 2; i++)
        #pragma unroll
        for (int j = 0; j < 8; j++)
            #pragma unroll
            for (int k = 0; k < 4; k++) acc[i][j][k] = 0.f;

    // staging: thread copies 4x16B per operand per chunk
    auto stage = [&](int kc, int buf) {
        const uint32_t sbuf = sb + buf * BUF_BYTES;
        #pragma unroll
        for (int v = 0; v < 4; v++) {
            const int soff = v * 4096 + tid * 16;
            const int e = soff >> 9, within = soff & 511;
            // A: tile_m = by*8 + (e>>2), tk = kc*4 + (e&3)
            const size_t ga = ((((size_t)(by * 8 + (e >> 2)) * 32) + kc * 4 + (e & 3)) << 9) + within;
            cp_async16(sbuf + soff, (const char*)g_Aperm + ga);
            const size_t gb = ((((size_t)(bx * 8 + (e >> 2)) * 32) + kc * 4 + (e & 3)) << 9) + within;
            cp_async16(sbuf + OPND_BYTES + soff, (const char*)g_Bperm + gb);
        }
    };

    stage(0, 0);
    CP_COMMIT();

    #pragma unroll
    for (int kc = 0; kc < 8; kc++) {
        if (kc < 7) {
            stage(kc + 1, (kc + 1) & 1);
            CP_COMMIT();
            CP_WAIT(1);
        } else {
            CP_WAIT(0);
        }
        __syncthreads();

        const uint4* As = (const uint4*)(smem + (kc & 1) * BUF_BYTES);
        const uint4* Bs = (const uint4*)(smem + (kc & 1) * BUF_BYTES + OPND_BYTES);

        #pragma unroll
        for (int ks = 0; ks < 4; ks++) {
            uint4 a[2], b[4];
            #pragma unroll
            for (int mt = 0; mt < 2; mt++)
                a[mt] = As[((warp_m * 2 + mt) * 4 + ks) * 32 + lane];
            #pragma unroll
            for (int pp = 0; pp < 4; pp++)
                b[pp] = Bs[((warp_n * 4 + pp) * 4 + ks) * 32 + lane];
            #pragma unroll
            for (int mt = 0; mt < 2; mt++)
                #pragma unroll
                for (int pp = 0; pp < 4; pp++) {
                    mma_tf32(acc[mt][2 * pp],     a[mt].x, a[mt].y, a[mt].z, a[mt].w, b[pp].x, b[pp].y);
                    mma_tf32(acc[mt][2 * pp + 1], a[mt].x, a[mt].y, a[mt].z, a[mt].w, b[pp].z, b[pp].w);
                }
        }
        __syncthreads();
    }

    // epilogue: L2 -> 5-kernel exp sum
    const float inv_b16 = g_inv_b16;
    float si[2][2];
    #pragma unroll
    for (int mt = 0; mt < 2; mt++) {
        const int r0 = by * 128 + warp_m * 32 + mt * 16 + g;
        si[mt][0] = g_sq[r0];
        si[mt][1] = g_sq[r0 + 8];
    }

    float ksum = 0.f;
    #pragma unroll
    for (int nt = 0; nt < 8; nt++) {
        const int c0 = warp_n * 64 + nt * 8 + 2 * t;
        const float tj0 = tjs[c0], tj1 = tjs[c0 + 1];
        #pragma unroll
        for (int mt = 0; mt < 2; mt++) {
            const float* c = acc[mt][nt];
            #pragma unroll
            for (int q = 0; q < 4; q++) {
                const float L2 = si[mt][q >> 1] + ((q & 1) ? tj1 : tj0) - 2.f * c[q];
                const float e = __expf(-L2 * inv_b16);
                const float e2 = e * e, e4 = e2 * e2, e8 = e4 * e4;
                ksum += e + e2 + e4 + e8 + e8 * e8;
            }
        }
    }

    #pragma unroll
    for (int off = 16; off > 0; off >>= 1) ksum += __shfl_xor_sync(0xffffffffu, ksum, off);
    float* red = (float*)(smem + SMEM_RED);
    if (lane == 0) red[wid] = ksum;
    __syncthreads();
    if (tid == 0) {
        float bsum = 0.f;
        #pragma unroll
        for (int i = 0; i < 8; i++) bsum += red[i];
        g_part[by * 32 + bx] = bsum;
    }

    // last-CTA tail: final loss
    __shared__ int is_last;
    __threadfence();
    if (tid == 0) is_last = (atomicAdd(&g_ctr2, 1) == 1023);
    __syncthreads();
    if (!is_last) return;
    __threadfence();

    double sacc = 0.0;
    #pragma unroll
    for (int m = 0; m < 4; m++) sacc += (double)g_part[tid + m * 256];
    __shared__ double dred[256];
    dred[tid] = sacc;
    __syncthreads();
    for (int st = 128; st > 0; st >>= 1) {
        if (tid < st) dred[tid] += dred[tid + st];
        __syncthreads();
    }
    if (tid == 0) {
        double mean = dred[0] / ((double)NROWS * (double)NROWS);
        out[0] = (float)(-2.0 * mean);
        g_ctr2 = 0;   // reset for graph replay
    }
}

// ---------------------------------------------------------------------------
extern "C" void kernel_launch(void* const* d_in, const int* in_sizes, int n_in,
                              void* d_out, int out_size) {
    (void)in_sizes; (void)n_in; (void)out_size;
    const float* src = (const float*)d_in[0];
    const float* tgt = (const float*)d_in[1];
    float* out = (float*)d_out;

    cudaFuncSetAttribute(mmd_mma_kernel, cudaFuncAttributeMaxDynamicSharedMemorySize,
                         SMEM_TOT);

    stats_kernel<<<64, 256>>>(src, tgt);
    mmd_mma_kernel<<<dim3(32, 32), 256, SMEM_TOT>>>(out);
}